// round 7
// baseline (speedup 1.0000x reference)
#include <cuda_runtime.h>
#include <cuda_fp16.h>
#include <stdint.h>

#define N_NODES 100000
#define N_SEGMENTS 250000
#define N_EDGES_MAX 2000000
#define D_FEAT 128
#define SCAN_TILE 1024
#define N_SCAN_BLOCKS ((N_SEGMENTS + SCAN_TILE - 1) / SCAN_TILE)   // 245

// ---- device-global scratch (no allocations) --------------------------------
// Invariant: g_hist == 0 on kernel_launch entry. True at load (zero-init),
// restored by pool_kernel at the end of every launch. g_cursor is overwritten
// by scan_kernel each launch; g_scan_done self-resets.
__device__ int      g_hist[N_SEGMENTS];
__device__ int      g_cursor[N_SEGMENTS];        // scan: intra-block prefix; reorder: bumps it
__device__ int      g_blocksums[256];            // block sums -> exclusive scanned
__device__ int      g_sorted_nid[N_EDGES_MAX];
__device__ int      g_idx_is_i64;                // for later kernels
__device__ unsigned g_scan_done;
__device__ __half   g_feat16[(size_t)N_NODES * D_FEAT];   // 25.6 MB fp16 table

// helper: detect packed-int64 layout from the first 64 odd 32-bit words
__device__ __forceinline__ int detect_i64(const int* ids32) {
    int acc = 0;
    #pragma unroll
    for (int i = 0; i < 64; i++) acc |= ids32[2 * i + 1];
    return (acc == 0) ? 1 : 0;
}

// ---------------------------------------------------------------------------
// 1) fused: dtype detect + histogram + f32->f16 table convert
//    (g_hist arrives zeroed — see invariant above)
// ---------------------------------------------------------------------------
__global__ void init_hist_convert_kernel(const float4* __restrict__ node_feat,
                                         const int* __restrict__ macro_ids,
                                         int n_edges) {
    const int stride = gridDim.x * blockDim.x;
    const int gtid = blockIdx.x * blockDim.x + threadIdx.x;

    // per-block local detect (no cross-block ordering needed)
    const int step = detect_i64(macro_ids) ? 2 : 1;
    if (gtid == 0) g_idx_is_i64 = (step == 2);   // for reorder_kernel

    // histogram
    for (int e = gtid; e < n_edges; e += stride) {
        const int mid = macro_ids[e * step];
        if ((unsigned)mid < (unsigned)N_SEGMENTS)
            atomicAdd(&g_hist[mid], 1);
    }

    // convert: float4 -> 2x half2
    const int n4 = N_NODES * D_FEAT / 4;          // 3.2M
    uint2* dst = (uint2*)g_feat16;
    for (int i = gtid; i < n4; i += stride) {
        const float4 v = __ldg(node_feat + i);
        const __half2 lo = __floats2half2_rn(v.x, v.y);
        const __half2 hi = __floats2half2_rn(v.z, v.w);
        uint2 o;
        o.x = *(const unsigned*)&lo;
        o.y = *(const unsigned*)&hi;
        dst[i] = o;
    }
}

// ---------------------------------------------------------------------------
// 2) scan: per-block exclusive scan into g_cursor (4 elems/thread, shuffles);
//    the LAST block additionally scans the 245 block sums.
// ---------------------------------------------------------------------------
__global__ void scan_kernel() {
    __shared__ int warp_sums[8];
    __shared__ int s_is_last;
    const int t = threadIdx.x;
    const int lane = t & 31;
    const int warp = t >> 5;
    const int base = blockIdx.x * SCAN_TILE + t * 4;

    int4 v = make_int4(0, 0, 0, 0);
    if (base + 3 < N_SEGMENTS) {
        v = *(const int4*)&g_hist[base];
    } else if (base < N_SEGMENTS) {
        v.x = g_hist[base];
        if (base + 1 < N_SEGMENTS) v.y = g_hist[base + 1];
        if (base + 2 < N_SEGMENTS) v.z = g_hist[base + 2];
    }

    const int s1 = v.x;
    const int s2 = s1 + v.y;
    const int s3 = s2 + v.z;
    const int s4 = s3 + v.w;

    int ws = s4;
    #pragma unroll
    for (int d = 1; d < 32; d <<= 1) {
        int up = __shfl_up_sync(0xffffffffu, ws, d);
        if (lane >= d) ws += up;
    }
    if (lane == 31) warp_sums[warp] = ws;
    __syncthreads();

    if (warp == 0 && lane < 8) {
        int x = warp_sums[lane];
        #pragma unroll
        for (int d = 1; d < 8; d <<= 1) {
            int up = __shfl_up_sync(0xffu, x, d);
            if (lane >= d) x += up;
        }
        warp_sums[lane] = x;
    }
    __syncthreads();

    const int warp_base = (warp > 0) ? warp_sums[warp - 1] : 0;
    const int pre = warp_base + (ws - s4);

    if (base + 3 < N_SEGMENTS) {
        int4 o = make_int4(pre, pre + s1, pre + s2, pre + s3);
        *(int4*)&g_cursor[base] = o;
    } else if (base < N_SEGMENTS) {
        g_cursor[base] = pre;
        if (base + 1 < N_SEGMENTS) g_cursor[base + 1] = pre + s1;
        if (base + 2 < N_SEGMENTS) g_cursor[base + 2] = pre + s2;
    }
    if (t == 255) g_blocksums[blockIdx.x] = warp_sums[7];

    // last-block fused scan of block sums
    __threadfence();
    if (t == 0) {
        const unsigned old = atomicAdd(&g_scan_done, 1);
        s_is_last = (old == gridDim.x - 1);
        if (s_is_last) g_scan_done = 0;
    }
    __syncthreads();
    if (s_is_last && warp == 0) {
        __threadfence();
        int vv[8];
        #pragma unroll
        for (int i = 0; i < 8; i++) {
            const int idx = lane * 8 + i;
            vv[i] = (idx < N_SCAN_BLOCKS) ? g_blocksums[idx] : 0;
        }
        int s = 0;
        #pragma unroll
        for (int i = 0; i < 8; i++) { const int tmp = vv[i]; vv[i] = s; s += tmp; }
        int w = s;
        #pragma unroll
        for (int d = 1; d < 32; d <<= 1) {
            int up = __shfl_up_sync(0xffffffffu, w, d);
            if (lane >= d) w += up;
        }
        const int b0 = w - s;
        #pragma unroll
        for (int i = 0; i < 8; i++) {
            const int idx = lane * 8 + i;
            if (idx < N_SCAN_BLOCKS) g_blocksums[idx] = b0 + vv[i];
        }
    }
}

// ---------------------------------------------------------------------------
// 3) reorder: 4 independent edge chains per iteration for MLP.
//    pos = blocksums[mid>>10] (L1-resident 1KB) + atomicAdd(cursor[mid])
// ---------------------------------------------------------------------------
__global__ void reorder_kernel(const int* __restrict__ node_ids,
                               const int* __restrict__ macro_ids,
                               int n_edges, int n_nodes) {
    const int step = g_idx_is_i64 ? 2 : 1;
    const int T = gridDim.x * blockDim.x;
    const int gtid = blockIdx.x * blockDim.x + threadIdx.x;

    int e = gtid;
    for (; e + 3 * T < n_edges; e += 4 * T) {
        int mid[4], nid[4];
        #pragma unroll
        for (int k = 0; k < 4; k++) {
            mid[k] = macro_ids[(e + k * T) * step];
            nid[k] = node_ids[(e + k * T) * step];
        }
        int pos[4];
        #pragma unroll
        for (int k = 0; k < 4; k++)
            pos[k] = g_blocksums[mid[k] >> 10] + atomicAdd(&g_cursor[mid[k]], 1);
        #pragma unroll
        for (int k = 0; k < 4; k++) {
            const int val = ((unsigned)nid[k] < (unsigned)n_nodes) ? nid[k] : 0;
            __stcs(&g_sorted_nid[pos[k]], val);
        }
    }
    for (; e < n_edges; e += T) {
        const int mid = macro_ids[e * step];
        const int nid = node_ids[e * step];
        if ((unsigned)mid >= (unsigned)N_SEGMENTS) continue;
        const int pos = g_blocksums[mid >> 10] + atomicAdd(&g_cursor[mid], 1);
        __stcs(&g_sorted_nid[pos], ((unsigned)nid < (unsigned)n_nodes) ? nid : 0);
    }
}

// ---------------------------------------------------------------------------
// 4) pooling: one warp per segment, fp16 gather, f32 accumulate.
//    Offset reconstructed as cursor_after - cnt. Resets g_hist for the
//    next launch (scratch invariant).
// ---------------------------------------------------------------------------
__global__ void pool_kernel(float4* __restrict__ out, int n_seg) {
    const int gtid = blockIdx.x * blockDim.x + threadIdx.x;
    const int seg  = gtid >> 5;
    const int lane = gtid & 31;
    if (seg >= n_seg) return;

    const int cnt = g_hist[seg];
    const int off = g_blocksums[seg >> 10] + g_cursor[seg] - cnt;  // cursor_after = pre+cnt

    if (lane == 0) g_hist[seg] = 0;       // restore invariant for next launch

    const uint2* feat = (const uint2*)g_feat16;   // row stride = 32 uint2

    float4 acc = make_float4(0.f, 0.f, 0.f, 0.f);

    for (int base = 0; base < cnt; base += 32) {
        const int rem = cnt - base;
        const int m = rem < 32 ? rem : 32;
        const int myid = (lane < rem) ? __ldcs(&g_sorted_nid[off + base + lane]) : 0;
        #pragma unroll 4
        for (int j = 0; j < m; j++) {
            const int nid = __shfl_sync(0xffffffffu, myid, j);
            const uint2 h = __ldg(feat + (long long)nid * 32 + lane);
            const float2 lo = __half22float2(*(const __half2*)&h.x);
            const float2 hi = __half22float2(*(const __half2*)&h.y);
            acc.x += lo.x; acc.y += lo.y; acc.z += hi.x; acc.w += hi.y;
        }
    }

    const float inv = 1.0f / fmaxf((float)cnt, 1.0f);
    acc.x *= inv; acc.y *= inv; acc.z *= inv; acc.w *= inv;
    __stcs(out + (long long)seg * 32 + lane, acc);
}

// ---------------------------------------------------------------------------
// Launch. Inputs: [0] node_feature f32 [100000,128], [1] batch_node_ids,
// [2] batch_macro_node_ids (int32 or packed int64 — detected on device).
// Output: f32 [250000, 128].
// ---------------------------------------------------------------------------
extern "C" void kernel_launch(void* const* d_in, const int* in_sizes, int n_in,
                              void* d_out, int out_size) {
    const float4* node_feat = (const float4*)d_in[0];
    const int*    node_ids  = (const int*)d_in[1];
    const int*    macro_ids = (const int*)d_in[2];
    float4*       out       = (float4*)d_out;

    const int n_edges = in_sizes[1] >= N_EDGES_MAX ? N_EDGES_MAX : in_sizes[1];
    const int n_nodes = in_sizes[0] / D_FEAT;     // 100000
    const int n_seg   = out_size / D_FEAT;        // 250000

    init_hist_convert_kernel<<<2048, 256>>>(node_feat, macro_ids, n_edges);
    scan_kernel<<<N_SCAN_BLOCKS, 256>>>();
    reorder_kernel<<<512, 256>>>(node_ids, macro_ids, n_edges, n_nodes);

    const long long total = (long long)n_seg * 32;
    pool_kernel<<<(int)((total + 255) / 256), 256>>>(out, n_seg);
}

// round 8
// speedup vs baseline: 1.7990x; 1.7990x over previous
#include <cuda_runtime.h>
#include <cuda_fp16.h>
#include <stdint.h>

#define N_NODES 100000
#define N_SEGMENTS 250000
#define N_EDGES_MAX 2000000
#define D_FEAT 128
#define SCAN_TILE 1024
#define N_SCAN_BLOCKS ((N_SEGMENTS + SCAN_TILE - 1) / SCAN_TILE)   // 245

// ---- device-global scratch (no allocations) --------------------------------
__device__ int      g_hist[N_SEGMENTS];
__device__ int      g_offsets[N_SEGMENTS];       // exclusive scan (intra-block part)
__device__ int      g_cursor[N_SEGMENTS];        // seeded by scan, bumped by reorder
__device__ int      g_blocksums[256];            // block sums -> exclusive scanned
__device__ int      g_sorted_nid[N_EDGES_MAX];
__device__ int      g_idx_is_i64;
__device__ unsigned g_scan_done;
__device__ __half   g_feat16[(size_t)N_NODES * D_FEAT];   // 25.6 MB fp16 table

__device__ __forceinline__ int detect_i64(const int* ids32) {
    int acc = 0;
    #pragma unroll
    for (int i = 0; i < 64; i++) acc |= ids32[2 * i + 1];
    return (acc == 0) ? 1 : 0;
}

// ---------------------------------------------------------------------------
// 1) init: detect index dtype + zero hist + f32->f16 table convert
// ---------------------------------------------------------------------------
__global__ void init_convert_kernel(const float4* __restrict__ node_feat,
                                    const int* __restrict__ ids32) {
    const int stride = gridDim.x * blockDim.x;
    const int gtid = blockIdx.x * blockDim.x + threadIdx.x;

    if (gtid == 0) g_idx_is_i64 = detect_i64(ids32);

    for (int i = gtid; i < N_SEGMENTS; i += stride)
        g_hist[i] = 0;

    const int n4 = N_NODES * D_FEAT / 4;          // 3.2M float4
    uint2* dst = (uint2*)g_feat16;
    for (int i = gtid; i < n4; i += stride) {
        const float4 v = __ldg(node_feat + i);
        const __half2 lo = __floats2half2_rn(v.x, v.y);
        const __half2 hi = __floats2half2_rn(v.z, v.w);
        uint2 o;
        o.x = *(const unsigned*)&lo;
        o.y = *(const unsigned*)&hi;
        dst[i] = o;
    }
}

// ---------------------------------------------------------------------------
// 2) histogram macro ids (per-block local dtype detect: no ordering needed)
// ---------------------------------------------------------------------------
__global__ void hist_kernel(const int* __restrict__ macro_ids, int n_edges) {
    const int step = detect_i64(macro_ids) ? 2 : 1;
    const int stride = gridDim.x * blockDim.x;
    for (int e = blockIdx.x * blockDim.x + threadIdx.x; e < n_edges; e += stride) {
        const int mid = macro_ids[e * step];
        if ((unsigned)mid < (unsigned)N_SEGMENTS)
            atomicAdd(&g_hist[mid], 1);
    }
}

// ---------------------------------------------------------------------------
// 3) scan: per-block exclusive scan -> g_offsets AND seeds g_cursor = pre.
//    LAST block additionally scans the 245 block sums (fused scan2).
// ---------------------------------------------------------------------------
__global__ void scan_kernel() {
    __shared__ int warp_sums[8];
    __shared__ int s_is_last;
    const int t = threadIdx.x;
    const int lane = t & 31;
    const int warp = t >> 5;
    const int base = blockIdx.x * SCAN_TILE + t * 4;

    int4 v = make_int4(0, 0, 0, 0);
    if (base + 3 < N_SEGMENTS) {
        v = *(const int4*)&g_hist[base];
    } else if (base < N_SEGMENTS) {
        v.x = g_hist[base];
        if (base + 1 < N_SEGMENTS) v.y = g_hist[base + 1];
        if (base + 2 < N_SEGMENTS) v.z = g_hist[base + 2];
    }

    const int s1 = v.x;
    const int s2 = s1 + v.y;
    const int s3 = s2 + v.z;
    const int s4 = s3 + v.w;

    int ws = s4;
    #pragma unroll
    for (int d = 1; d < 32; d <<= 1) {
        int up = __shfl_up_sync(0xffffffffu, ws, d);
        if (lane >= d) ws += up;
    }
    if (lane == 31) warp_sums[warp] = ws;
    __syncthreads();

    if (warp == 0 && lane < 8) {
        int x = warp_sums[lane];
        #pragma unroll
        for (int d = 1; d < 8; d <<= 1) {
            int up = __shfl_up_sync(0xffu, x, d);
            if (lane >= d) x += up;
        }
        warp_sums[lane] = x;
    }
    __syncthreads();

    const int warp_base = (warp > 0) ? warp_sums[warp - 1] : 0;
    const int pre = warp_base + (ws - s4);

    if (base + 3 < N_SEGMENTS) {
        int4 o = make_int4(pre, pre + s1, pre + s2, pre + s3);
        *(int4*)&g_offsets[base] = o;
        *(int4*)&g_cursor[base]  = o;     // seed reorder cursors
    } else if (base < N_SEGMENTS) {
        g_offsets[base] = pre;             g_cursor[base] = pre;
        if (base + 1 < N_SEGMENTS) { g_offsets[base + 1] = pre + s1; g_cursor[base + 1] = pre + s1; }
        if (base + 2 < N_SEGMENTS) { g_offsets[base + 2] = pre + s2; g_cursor[base + 2] = pre + s2; }
    }
    if (t == 255) g_blocksums[blockIdx.x] = warp_sums[7];

    // last-block fused scan of block sums
    __threadfence();
    if (t == 0) {
        const unsigned old = atomicAdd(&g_scan_done, 1);
        s_is_last = (old == gridDim.x - 1);
        if (s_is_last) g_scan_done = 0;
    }
    __syncthreads();
    if (s_is_last && warp == 0) {
        __threadfence();
        int vv[8];
        #pragma unroll
        for (int i = 0; i < 8; i++) {
            const int idx = lane * 8 + i;
            vv[i] = (idx < N_SCAN_BLOCKS) ? g_blocksums[idx] : 0;
        }
        int s = 0;
        #pragma unroll
        for (int i = 0; i < 8; i++) { const int tmp = vv[i]; vv[i] = s; s += tmp; }
        int w = s;
        #pragma unroll
        for (int d = 1; d < 32; d <<= 1) {
            int up = __shfl_up_sync(0xffffffffu, w, d);
            if (lane >= d) w += up;
        }
        const int b0 = w - s;
        #pragma unroll
        for (int i = 0; i < 8; i++) {
            const int idx = lane * 8 + i;
            if (idx < N_SCAN_BLOCKS) g_blocksums[idx] = b0 + vv[i];
        }
    }
}

// ---------------------------------------------------------------------------
// 4) reorder: 4 independent edge chains per iteration for MLP.
//    pos = blocksums[mid>>10] (1KB, L1-resident) + atomicAdd(cursor[mid])
// ---------------------------------------------------------------------------
__global__ void reorder_kernel(const int* __restrict__ node_ids,
                               const int* __restrict__ macro_ids,
                               int n_edges, int n_nodes) {
    const int step = g_idx_is_i64 ? 2 : 1;
    const int T = gridDim.x * blockDim.x;
    const int gtid = blockIdx.x * blockDim.x + threadIdx.x;

    int e = gtid;
    for (; e + 3 * T < n_edges; e += 4 * T) {
        int mid[4], nid[4];
        #pragma unroll
        for (int k = 0; k < 4; k++) {
            mid[k] = macro_ids[(e + k * T) * step];
            nid[k] = node_ids[(e + k * T) * step];
        }
        int pos[4];
        #pragma unroll
        for (int k = 0; k < 4; k++)
            pos[k] = g_blocksums[mid[k] >> 10] + atomicAdd(&g_cursor[mid[k]], 1);
        #pragma unroll
        for (int k = 0; k < 4; k++) {
            const int val = ((unsigned)nid[k] < (unsigned)n_nodes) ? nid[k] : 0;
            __stcs(&g_sorted_nid[pos[k]], val);
        }
    }
    for (; e < n_edges; e += T) {
        const int mid = macro_ids[e * step];
        const int nid = node_ids[e * step];
        if ((unsigned)mid >= (unsigned)N_SEGMENTS) continue;
        const int pos = g_blocksums[mid >> 10] + atomicAdd(&g_cursor[mid], 1);
        __stcs(&g_sorted_nid[pos], ((unsigned)nid < (unsigned)n_nodes) ? nid : 0);
    }
}

// ---------------------------------------------------------------------------
// 5) pooling — EXACT body of the 133.9us-measured version (do not touch).
// ---------------------------------------------------------------------------
__global__ void pool_kernel(float4* __restrict__ out, int n_seg) {
    const int gtid = blockIdx.x * blockDim.x + threadIdx.x;
    const int seg  = gtid >> 5;
    const int lane = gtid & 31;
    if (seg >= n_seg) return;

    const int off = g_offsets[seg] + g_blocksums[seg >> 10];
    const int cnt = g_hist[seg];

    const uint2* feat = (const uint2*)g_feat16;   // row stride = 32 uint2

    float4 acc = make_float4(0.f, 0.f, 0.f, 0.f);

    for (int base = 0; base < cnt; base += 32) {
        const int rem = cnt - base;
        const int m = rem < 32 ? rem : 32;
        const int myid = (lane < rem) ? __ldcs(&g_sorted_nid[off + base + lane]) : 0;
        #pragma unroll 4
        for (int j = 0; j < m; j++) {
            const int nid = __shfl_sync(0xffffffffu, myid, j);
            const uint2 h = __ldg(feat + (long long)nid * 32 + lane);
            const float2 lo = __half22float2(*(const __half2*)&h.x);
            const float2 hi = __half22float2(*(const __half2*)&h.y);
            acc.x += lo.x; acc.y += lo.y; acc.z += hi.x; acc.w += hi.y;
        }
    }

    const float inv = 1.0f / fmaxf((float)cnt, 1.0f);
    acc.x *= inv; acc.y *= inv; acc.z *= inv; acc.w *= inv;
    __stcs(out + (long long)seg * 32 + lane, acc);
}

// ---------------------------------------------------------------------------
// Launch. Inputs: [0] node_feature f32 [100000,128], [1] batch_node_ids,
// [2] batch_macro_node_ids (int32 or packed int64 — detected on device).
// Output: f32 [250000, 128].
// ---------------------------------------------------------------------------
extern "C" void kernel_launch(void* const* d_in, const int* in_sizes, int n_in,
                              void* d_out, int out_size) {
    const float4* node_feat = (const float4*)d_in[0];
    const int*    node_ids  = (const int*)d_in[1];
    const int*    macro_ids = (const int*)d_in[2];
    float4*       out       = (float4*)d_out;

    const int n_edges = in_sizes[1] >= N_EDGES_MAX ? N_EDGES_MAX : in_sizes[1];
    const int n_nodes = in_sizes[0] / D_FEAT;     // 100000
    const int n_seg   = out_size / D_FEAT;        // 250000

    init_convert_kernel<<<2048, 256>>>(node_feat, node_ids);
    hist_kernel<<<2048, 256>>>(macro_ids, n_edges);
    scan_kernel<<<N_SCAN_BLOCKS, 256>>>();
    reorder_kernel<<<512, 256>>>(node_ids, macro_ids, n_edges, n_nodes);

    const long long total = (long long)n_seg * 32;
    pool_kernel<<<(int)((total + 255) / 256), 256>>>(out, n_seg);
}

// round 9
// speedup vs baseline: 1.8628x; 1.0355x over previous
#include <cuda_runtime.h>
#include <cuda_fp16.h>
#include <stdint.h>

#define N_NODES 100000
#define N_SEGMENTS 250000
#define N_EDGES_MAX 2000000
#define D_FEAT 128
#define SCAN_TILE 1024
#define N_SCAN_BLOCKS ((N_SEGMENTS + SCAN_TILE - 1) / SCAN_TILE)   // 245

// ---- device-global scratch (no allocations) --------------------------------
__device__ int      g_hist[N_SEGMENTS];
__device__ int      g_offsets[N_SEGMENTS];       // exclusive scan (intra-block part)
__device__ int      g_rank[N_EDGES_MAX];         // edge rank within its segment
__device__ int      g_blocksums[256];            // block sums -> exclusive scanned
__device__ int      g_sorted_nid[N_EDGES_MAX];
__device__ int      g_idx_is_i64;
__device__ unsigned g_scan_done;
__device__ __half   g_feat16[(size_t)N_NODES * D_FEAT];   // 25.6 MB fp16 table

__device__ __forceinline__ int detect_i64(const int* ids32) {
    int acc = 0;
    #pragma unroll
    for (int i = 0; i < 64; i++) acc |= ids32[2 * i + 1];
    return (acc == 0) ? 1 : 0;
}

// ---------------------------------------------------------------------------
// 1) init: detect index dtype + zero hist + f32->f16 table convert
// ---------------------------------------------------------------------------
__global__ void init_convert_kernel(const float4* __restrict__ node_feat,
                                    const int* __restrict__ ids32) {
    const int stride = gridDim.x * blockDim.x;
    const int gtid = blockIdx.x * blockDim.x + threadIdx.x;

    if (gtid == 0) g_idx_is_i64 = detect_i64(ids32);

    for (int i = gtid; i < N_SEGMENTS; i += stride)
        g_hist[i] = 0;

    const int n4 = N_NODES * D_FEAT / 4;          // 3.2M float4
    uint2* dst = (uint2*)g_feat16;
    for (int i = gtid; i < n4; i += stride) {
        const float4 v = __ldg(node_feat + i);
        const __half2 lo = __floats2half2_rn(v.x, v.y);
        const __half2 hi = __floats2half2_rn(v.z, v.w);
        uint2 o;
        o.x = *(const unsigned*)&lo;
        o.y = *(const unsigned*)&hi;
        dst[i] = o;
    }
}

// ---------------------------------------------------------------------------
// 2) histogram macro ids — KEEP the atomic's return value as the edge rank.
// ---------------------------------------------------------------------------
__global__ void hist_kernel(const int* __restrict__ macro_ids, int n_edges) {
    const int step = detect_i64(macro_ids) ? 2 : 1;
    const int stride = gridDim.x * blockDim.x;
    for (int e = blockIdx.x * blockDim.x + threadIdx.x; e < n_edges; e += stride) {
        const int mid = macro_ids[e * step];
        int r = 0;
        if ((unsigned)mid < (unsigned)N_SEGMENTS)
            r = atomicAdd(&g_hist[mid], 1);
        g_rank[e] = r;                    // coalesced store
    }
}

// ---------------------------------------------------------------------------
// 3) scan: per-block exclusive scan -> g_offsets.
//    LAST block additionally scans the 245 block sums (fused scan2).
// ---------------------------------------------------------------------------
__global__ void scan_kernel() {
    __shared__ int warp_sums[8];
    __shared__ int s_is_last;
    const int t = threadIdx.x;
    const int lane = t & 31;
    const int warp = t >> 5;
    const int base = blockIdx.x * SCAN_TILE + t * 4;

    int4 v = make_int4(0, 0, 0, 0);
    if (base + 3 < N_SEGMENTS) {
        v = *(const int4*)&g_hist[base];
    } else if (base < N_SEGMENTS) {
        v.x = g_hist[base];
        if (base + 1 < N_SEGMENTS) v.y = g_hist[base + 1];
        if (base + 2 < N_SEGMENTS) v.z = g_hist[base + 2];
    }

    const int s1 = v.x;
    const int s2 = s1 + v.y;
    const int s3 = s2 + v.z;
    const int s4 = s3 + v.w;

    int ws = s4;
    #pragma unroll
    for (int d = 1; d < 32; d <<= 1) {
        int up = __shfl_up_sync(0xffffffffu, ws, d);
        if (lane >= d) ws += up;
    }
    if (lane == 31) warp_sums[warp] = ws;
    __syncthreads();

    if (warp == 0 && lane < 8) {
        int x = warp_sums[lane];
        #pragma unroll
        for (int d = 1; d < 8; d <<= 1) {
            int up = __shfl_up_sync(0xffu, x, d);
            if (lane >= d) x += up;
        }
        warp_sums[lane] = x;
    }
    __syncthreads();

    const int warp_base = (warp > 0) ? warp_sums[warp - 1] : 0;
    const int pre = warp_base + (ws - s4);

    if (base + 3 < N_SEGMENTS) {
        int4 o = make_int4(pre, pre + s1, pre + s2, pre + s3);
        *(int4*)&g_offsets[base] = o;
    } else if (base < N_SEGMENTS) {
        g_offsets[base] = pre;
        if (base + 1 < N_SEGMENTS) g_offsets[base + 1] = pre + s1;
        if (base + 2 < N_SEGMENTS) g_offsets[base + 2] = pre + s2;
    }
    if (t == 255) g_blocksums[blockIdx.x] = warp_sums[7];

    // last-block fused scan of block sums
    __threadfence();
    if (t == 0) {
        const unsigned old = atomicAdd(&g_scan_done, 1);
        s_is_last = (old == gridDim.x - 1);
        if (s_is_last) g_scan_done = 0;
    }
    __syncthreads();
    if (s_is_last && warp == 0) {
        __threadfence();
        int vv[8];
        #pragma unroll
        for (int i = 0; i < 8; i++) {
            const int idx = lane * 8 + i;
            vv[i] = (idx < N_SCAN_BLOCKS) ? g_blocksums[idx] : 0;
        }
        int s = 0;
        #pragma unroll
        for (int i = 0; i < 8; i++) { const int tmp = vv[i]; vv[i] = s; s += tmp; }
        int w = s;
        #pragma unroll
        for (int d = 1; d < 32; d <<= 1) {
            int up = __shfl_up_sync(0xffffffffu, w, d);
            if (lane >= d) w += up;
        }
        const int b0 = w - s;
        #pragma unroll
        for (int i = 0; i < 8; i++) {
            const int idx = lane * 8 + i;
            if (idx < N_SCAN_BLOCKS) g_blocksums[idx] = b0 + vv[i];
        }
    }
}

// ---------------------------------------------------------------------------
// 4) reorder — ATOMIC-FREE: pos = offsets[mid] + blocksums[mid>>10] + rank[e].
//    Pure loads + scatter store; grid-stride at full occupancy for MLP.
// ---------------------------------------------------------------------------
__global__ void reorder_kernel(const int* __restrict__ node_ids,
                               const int* __restrict__ macro_ids,
                               int n_edges, int n_nodes) {
    const int step = g_idx_is_i64 ? 2 : 1;
    const int stride = gridDim.x * blockDim.x;
    for (int e = blockIdx.x * blockDim.x + threadIdx.x; e < n_edges; e += stride) {
        const int mid = macro_ids[e * step];
        const int nid = node_ids[e * step];
        if ((unsigned)mid >= (unsigned)N_SEGMENTS) continue;
        const int pos = g_offsets[mid] + g_blocksums[mid >> 10] + g_rank[e];
        const int val = ((unsigned)nid < (unsigned)n_nodes) ? nid : 0;
        __stcs(&g_sorted_nid[pos], val);
    }
}

// ---------------------------------------------------------------------------
// 5) pooling — EXACT body of the 133.9us-measured version (do not touch).
// ---------------------------------------------------------------------------
__global__ void pool_kernel(float4* __restrict__ out, int n_seg) {
    const int gtid = blockIdx.x * blockDim.x + threadIdx.x;
    const int seg  = gtid >> 5;
    const int lane = gtid & 31;
    if (seg >= n_seg) return;

    const int off = g_offsets[seg] + g_blocksums[seg >> 10];
    const int cnt = g_hist[seg];

    const uint2* feat = (const uint2*)g_feat16;   // row stride = 32 uint2

    float4 acc = make_float4(0.f, 0.f, 0.f, 0.f);

    for (int base = 0; base < cnt; base += 32) {
        const int rem = cnt - base;
        const int m = rem < 32 ? rem : 32;
        const int myid = (lane < rem) ? __ldcs(&g_sorted_nid[off + base + lane]) : 0;
        #pragma unroll 4
        for (int j = 0; j < m; j++) {
            const int nid = __shfl_sync(0xffffffffu, myid, j);
            const uint2 h = __ldg(feat + (long long)nid * 32 + lane);
            const float2 lo = __half22float2(*(const __half2*)&h.x);
            const float2 hi = __half22float2(*(const __half2*)&h.y);
            acc.x += lo.x; acc.y += lo.y; acc.z += hi.x; acc.w += hi.y;
        }
    }

    const float inv = 1.0f / fmaxf((float)cnt, 1.0f);
    acc.x *= inv; acc.y *= inv; acc.z *= inv; acc.w *= inv;
    __stcs(out + (long long)seg * 32 + lane, acc);
}

// ---------------------------------------------------------------------------
// Launch. Inputs: [0] node_feature f32 [100000,128], [1] batch_node_ids,
// [2] batch_macro_node_ids (int32 or packed int64 — detected on device).
// Output: f32 [250000, 128].
// ---------------------------------------------------------------------------
extern "C" void kernel_launch(void* const* d_in, const int* in_sizes, int n_in,
                              void* d_out, int out_size) {
    const float4* node_feat = (const float4*)d_in[0];
    const int*    node_ids  = (const int*)d_in[1];
    const int*    macro_ids = (const int*)d_in[2];
    float4*       out       = (float4*)d_out;

    const int n_edges = in_sizes[1] >= N_EDGES_MAX ? N_EDGES_MAX : in_sizes[1];
    const int n_nodes = in_sizes[0] / D_FEAT;     // 100000
    const int n_seg   = out_size / D_FEAT;        // 250000

    init_convert_kernel<<<2048, 256>>>(node_feat, node_ids);
    hist_kernel<<<2048, 256>>>(macro_ids, n_edges);
    scan_kernel<<<N_SCAN_BLOCKS, 256>>>();
    reorder_kernel<<<2048, 256>>>(node_ids, macro_ids, n_edges, n_nodes);

    const long long total = (long long)n_seg * 32;
    pool_kernel<<<(int)((total + 255) / 256), 256>>>(out, n_seg);
}